// round 8
// baseline (speedup 1.0000x reference)
#include <cuda_runtime.h>
#include <cuda_bf16.h>
#include <math_constants.h>

#define NPTS 16384
#define MCTR 4096
#define KNBR 32
#define FIN  64
#define RAD2 0.25f
#define MAXC 64

#define CLS  8       // FPS cluster size (CTAs)
#define TFPS 256     // threads per FPS CTA
#define PPT  8       // points per thread; CLS*TFPS*PPT == NPTS
#define NW   (TFPS / 32)

// ---------------- device scratch (no allocations allowed) ----------------
__device__ int g_idx[MCTR];
__device__ int g_nbr[MCTR * KNBR];
__device__ int g_cnt[MCTR];

__device__ __forceinline__ unsigned smem_u32(const void* p)
{
    unsigned a;
    asm("{ .reg .u64 t; cvta.to.shared.u64 t, %1; cvt.u32.u64 %0, t; }"
        : "=r"(a) : "l"(p));
    return a;
}
__device__ __forceinline__ void sts_vol_u64(unsigned a, unsigned long long v)
{
    asm volatile("st.volatile.shared.b64 [%0], %1;" :: "r"(a), "l"(v) : "memory");
}
__device__ __forceinline__ unsigned long long lds_vol_u64(unsigned a)
{
    unsigned long long v;
    asm volatile("ld.volatile.shared.b64 %0, [%1];" : "=l"(v) : "r"(a) : "memory");
    return v;
}

// ---------------- Stage 1: cluster-cooperative FPS, barrier-free iteration ----------------
// key = bits(val)<<32 | (0x3FFF - idx)<<12 | tag(12 bits = iteration)
// Single 8B words everywhere: tag + payload atomic. Receivers poll LOCAL smem.
__global__ __launch_bounds__(TFPS, 1) __cluster_dims__(CLS, 1, 1)
void fps_kernel(const float* __restrict__ pos)
{
    extern __shared__ float s_tab[];
    float* s_x = s_tab;
    float* s_y = s_tab + NPTS;
    float* s_z = s_tab + 2 * NPTS;

    __shared__ unsigned long long s_mbox[2][CLS];   // [parity][source CTA]
    __shared__ unsigned long long s_wkey[NW];       // per-warp tagged keys

    const int t    = threadIdx.x;
    const int w    = t >> 5;
    const int lane = t & 31;
    unsigned rank;
    asm("mov.u32 %0, %%cluster_ctarank;" : "=r"(rank));

    // one-time: local coordinate table + mailbox/wkey init
    for (int i = t; i < NPTS; i += TFPS) {
        s_x[i] = pos[i * 3 + 0];
        s_y[i] = pos[i * 3 + 1];
        s_z[i] = pos[i * 3 + 2];
    }
    if (t < 2 * CLS) s_mbox[t >> 3][t & (CLS - 1)] = 0ull;
    if (t < NW) s_wkey[t] = 0ull;
    if (rank == 0 && t == 0) g_idx[0] = 0;
    __syncthreads();
    asm volatile("barrier.cluster.arrive.aligned;" ::: "memory");
    asm volatile("barrier.cluster.wait.aligned;"   ::: "memory");

    const unsigned a_wkey_mine = smem_u32(&s_wkey[w]);
    const unsigned a_wkey_poll = smem_u32(&s_wkey[lane & (NW - 1)]);
    const unsigned a_mbox0     = smem_u32(&s_mbox[0][lane & (CLS - 1)]);
    const unsigned a_mbox1     = smem_u32(&s_mbox[1][lane & (CLS - 1)]);

    // this thread's PPT points: gi = base + t + j*TFPS (ascending in j)
    const int base = (int)rank * (TFPS * PPT) + t;
    float px[PPT], py[PPT], pz[PPT], dmin[PPT];
    #pragma unroll
    for (int j = 0; j < PPT; ++j) {
        int gi = base + j * TFPS;
        px[j] = s_x[gi]; py[j] = s_y[gi]; pz[j] = s_z[gi];
        dmin[j] = CUDART_INF_F;
    }
    float cx = s_x[0], cy = s_y[0], cz = s_z[0];

    for (int it = 1; it < MCTR; ++it) {
        // exact reference arithmetic: ((dx*dx + dy*dy) + dz*dz), all rn, no FMA
        // thread-local argmax with first-index tie-break (ascending gi, strict >)
        float bestv = -1.0f;
        int   bestj = 0;
        #pragma unroll
        for (int j = 0; j < PPT; ++j) {
            float dx = px[j] - cx, dy = py[j] - cy, dz = pz[j] - cz;
            float d = __fadd_rn(__fadd_rn(__fmul_rn(dx, dx), __fmul_rn(dy, dy)),
                                __fmul_rn(dz, dz));
            float dm = fminf(dmin[j], d);
            dmin[j] = dm;
            if (dm > bestv) { bestv = dm; bestj = j; }
        }
        int besti = base + bestj * TFPS;

        // warp argmax: max value (nonneg float bits monotone as u32), then min index
        unsigned vb   = __float_as_uint(bestv);
        unsigned wmax = __reduce_max_sync(0xffffffffu, vb);
        int cand = (vb == wmax) ? besti : 0x7fffffff;
        int wi   = __reduce_min_sync(0xffffffffu, cand);
        if (lane == 0)
            sts_vol_u64(a_wkey_mine,
                        ((unsigned long long)wmax << 32)
                      | ((unsigned long long)(0x3FFFu - (unsigned)wi) << 12)
                      | (unsigned)it);

        if (w == 0) {
            // collect 8 tagged warp keys via LDS polling (replaces bar.sync A)
            unsigned long long k;
            for (;;) {
                k = lds_vol_u64(a_wkey_poll);
                if (__all_sync(0xffffffffu, (unsigned)(k & 0xFFFu) == (unsigned)it))
                    break;
            }
            unsigned hi  = (unsigned)(k >> 32);
            unsigned bhi = __reduce_max_sync(0xffffffffu, hi);
            unsigned lo  = (hi == bhi) ? (unsigned)k : 0u;
            unsigned blo = __reduce_max_sync(0xffffffffu, lo);
            unsigned long long bkey =
                ((unsigned long long)bhi << 32) | (blo & 0xFFFFF000u) | (unsigned)it;

            // push our block key into every CTA's mailbox (8 remote stores in parallel)
            if (lane < CLS) {
                unsigned la = smem_u32(&s_mbox[it & 1][rank]);
                unsigned ra;
                asm("mapa.shared::cluster.u32 %0, %1, %2;"
                    : "=r"(ra) : "r"(la), "r"(lane));
                asm volatile("st.relaxed.cluster.shared::cluster.b64 [%0], %1;"
                             :: "r"(ra), "l"(bkey) : "memory");
            }
        }

        // ALL warps poll the LOCAL mailbox and reduce independently (replaces bar B)
        const unsigned pa = (it & 1) ? a_mbox1 : a_mbox0;
        unsigned long long r;
        for (;;) {
            r = lds_vol_u64(pa);
            if (__all_sync(0xffffffffu, (unsigned)(r & 0xFFFu) == (unsigned)it))
                break;
        }
        unsigned hi2  = (unsigned)(r >> 32);
        unsigned gmax = __reduce_max_sync(0xffffffffu, hi2);
        unsigned lo2  = (hi2 == gmax) ? (unsigned)r : 0u;
        unsigned glo  = __reduce_max_sync(0xffffffffu, lo2);
        int gidx = (int)(0x3FFFu - ((glo >> 12) & 0x3FFFu));

        if (rank == 0 && w == 0 && lane == 0) g_idx[it] = gidx;  // fire-and-forget

        cx = s_x[gidx]; cy = s_y[gidx]; cz = s_z[gidx];          // broadcast LDS
    }

    // no CTA may exit while peers could still target its smem
    asm volatile("barrier.cluster.arrive.aligned;" ::: "memory");
    asm volatile("barrier.cluster.wait.aligned;"   ::: "memory");
}

// ---------------- Stage 2: ball query ----------------
#define CHUNK 2048
__global__ __launch_bounds__(256)
void nbr_kernel(const float* __restrict__ pos)
{
    __shared__ float sx[CHUNK], sy[CHUNK], sz[CHUNK];
    __shared__ int   s_ci[8][MAXC];
    __shared__ float s_cd[8][MAXC];

    const int tid  = threadIdx.x;
    const int w    = tid >> 5;
    const int lane = tid & 31;
    const int m    = blockIdx.x * 8 + w;

    const int cidx = g_idx[m];
    const float cx = pos[cidx * 3 + 0];
    const float cy = pos[cidx * 3 + 1];
    const float cz = pos[cidx * 3 + 2];

    int cnt = 0;
    for (int base = 0; base < NPTS; base += CHUNK) {
        __syncthreads();
        for (int i = tid; i < CHUNK; i += 256) {
            sx[i] = pos[(base + i) * 3 + 0];
            sy[i] = pos[(base + i) * 3 + 1];
            sz[i] = pos[(base + i) * 3 + 2];
        }
        __syncthreads();
        for (int i = lane; i < CHUNK; i += 32) {
            float dx = sx[i] - cx, dy = sy[i] - cy, dz = sz[i] - cz;
            float d2 = __fadd_rn(__fadd_rn(__fmul_rn(dx, dx), __fmul_rn(dy, dy)),
                                 __fmul_rn(dz, dz));
            bool in = (d2 <= RAD2);
            unsigned mk = __ballot_sync(0xffffffffu, in);
            int slot = cnt + __popc(mk & ((1u << lane) - 1u));
            if (in && slot < MAXC) { s_ci[w][slot] = base + i; s_cd[w][slot] = d2; }
            cnt += __popc(mk);
        }
    }
    cnt = min(cnt, MAXC);

    if (cnt <= KNBR) {
        if (lane < cnt) g_nbr[m * KNBR + lane] = s_ci[w][lane];
        if (lane == 0)  g_cnt[m] = cnt;
    } else {
        for (int c = lane; c < cnt; c += 32) {
            float d = s_cd[w][c];
            int  ii = s_ci[w][c];
            int r = 0;
            for (int o = 0; o < cnt; ++o) {
                float d2o = s_cd[w][o];
                r += (d2o < d) || (d2o == d && s_ci[w][o] < ii);
            }
            if (r < KNBR) g_nbr[m * KNBR + r] = ii;
        }
        if (lane == 0) g_cnt[m] = KNBR;
    }
}

// ---------------- Stage 3: per-edge MLP + masked max aggregation ----------------
__global__ __launch_bounds__(256)
void mlp_kernel(const float* __restrict__ feat,
                const float* __restrict__ pos,
                const float* __restrict__ W1, const float* __restrict__ b1,
                const float* __restrict__ W2, const float* __restrict__ b2,
                const float* __restrict__ W3, const float* __restrict__ b3,
                float* __restrict__ out)
{
    __shared__ float xb[32][68];
    __shared__ float h1[32][64];
    __shared__ float h2[32][64];
    __shared__ float h3[32][128];

    const int m    = blockIdx.x;
    const int tid  = threadIdx.x;
    const int w    = tid >> 5;
    const int lane = tid & 31;
    const int cnt  = g_cnt[m];

    const int cidx = g_idx[m];
    const float cx = pos[cidx * 3 + 0];
    const float cy = pos[cidx * 3 + 1];
    const float cz = pos[cidx * 3 + 2];

    for (int k = w; k < cnt; k += 8) {
        int j = g_nbr[m * KNBR + k];
        xb[k][lane]      = feat[j * FIN + lane];
        xb[k][lane + 32] = feat[j * FIN + lane + 32];
        if (lane == 0) {
            xb[k][64] = pos[j * 3 + 0] - cx;
            xb[k][65] = pos[j * 3 + 1] - cy;
            xb[k][66] = pos[j * 3 + 2] - cz;
        }
    }
    __syncthreads();

    for (int p = tid; p < cnt * 64; p += 256) {
        int k = p >> 6, o = p & 63;
        float acc = b1[o];
        #pragma unroll
        for (int i = 0; i < 67; ++i)
            acc = fmaf(xb[k][i], W1[i * 64 + o], acc);
        h1[k][o] = fmaxf(acc, 0.0f);
    }
    __syncthreads();

    for (int p = tid; p < cnt * 64; p += 256) {
        int k = p >> 6, o = p & 63;
        float acc = b2[o];
        #pragma unroll
        for (int i = 0; i < 64; ++i)
            acc = fmaf(h1[k][i], W2[i * 64 + o], acc);
        h2[k][o] = fmaxf(acc, 0.0f);
    }
    __syncthreads();

    for (int p = tid; p < cnt * 128; p += 256) {
        int k = p >> 7, o = p & 127;
        float acc = b3[o];
        #pragma unroll
        for (int i = 0; i < 64; ++i)
            acc = fmaf(h2[k][i], W3[i * 128 + o], acc);
        h3[k][o] = fmaxf(acc, 0.0f);
    }
    __syncthreads();

    if (tid < 128) {
        float mx = -CUDART_INF_F;
        for (int k = 0; k < cnt; ++k) mx = fmaxf(mx, h3[k][tid]);
        out[m * 128 + tid] = mx;
    }
}

// ---------------- Stage 4: tail outputs ----------------
__global__ void tail_kernel(const float* __restrict__ pos, float* __restrict__ out,
                            int out_size)
{
    int m = blockIdx.x * blockDim.x + threadIdx.x;
    if (m >= MCTR) return;
    const int base = MCTR * 128;
    if (out_size >= base + 3 * MCTR) {
        int j = g_idx[m];
        out[base + 3 * m + 0] = pos[3 * j + 0];
        out[base + 3 * m + 1] = pos[3 * j + 1];
        out[base + 3 * m + 2] = pos[3 * j + 2];
    }
    if (out_size >= base + 3 * MCTR + MCTR) {
        out[base + 3 * MCTR + m] = 0.0f;
    }
}

extern "C" void kernel_launch(void* const* d_in, const int* in_sizes, int n_in,
                              void* d_out, int out_size)
{
    const float* feat = (const float*)d_in[0];
    const float* pos  = (const float*)d_in[1];
    const float* W1 = (const float*)d_in[3];
    const float* b1 = (const float*)d_in[4];
    const float* W2 = (const float*)d_in[5];
    const float* b2 = (const float*)d_in[6];
    const float* W3 = (const float*)d_in[7];
    const float* b3 = (const float*)d_in[8];
    float* out = (float*)d_out;

    const size_t fps_smem = 3 * NPTS * sizeof(float);   // 192KB
    cudaFuncSetAttribute(fps_kernel, cudaFuncAttributeMaxDynamicSharedMemorySize,
                         (int)fps_smem);

    fps_kernel<<<CLS, TFPS, fps_smem>>>(pos);
    nbr_kernel<<<MCTR / 8, 256>>>(pos);
    mlp_kernel<<<MCTR, 256>>>(feat, pos, W1, b1, W2, b2, W3, b3, out);
    tail_kernel<<<(MCTR + 255) / 256, 256>>>(pos, out, out_size);
}

// round 9
// speedup vs baseline: 1.3734x; 1.3734x over previous
#include <cuda_runtime.h>
#include <cuda_bf16.h>
#include <math_constants.h>

#define NPTS 16384
#define MCTR 4096
#define KNBR 32
#define FIN  64
#define RAD2 0.25f
#define MAXC 64

#define CLS  8       // FPS cluster size (CTAs)
#define TFPS 256     // threads per FPS CTA
#define PPT  8       // points per thread; CLS*TFPS*PPT == NPTS
#define NW   (TFPS / 32)
#define NSLOT (CLS * NW)   // 64 warp-key slots per parity

// ---------------- device scratch (no allocations allowed) ----------------
__device__ int g_idx[MCTR];
__device__ int g_nbr[MCTR * KNBR];
__device__ int g_cnt[MCTR];

__device__ __forceinline__ unsigned smem_u32(const void* p)
{
    unsigned a;
    asm("{ .reg .u64 t; cvta.to.shared.u64 t, %1; cvt.u32.u64 %0, t; }"
        : "=r"(a) : "l"(p));
    return a;
}
__device__ __forceinline__ unsigned long long lds_vol_u64(unsigned a)
{
    unsigned long long v;
    asm volatile("ld.volatile.shared.b64 %0, [%1];" : "=l"(v) : "r"(a) : "memory");
    return v;
}

// ---------------- Stage 1: cluster-cooperative FPS, direct warp-key exchange ----------------
// key = bits(val)<<32 | (0x3FFF - idx)<<12 | tag(12 bits = iteration)
// All warps symmetric: warp-REDUX -> push warp key to all CTAs -> poll 64 local
// slots -> reduce 64->1 -> center lookup. No intra-block handoff on the chain.
__global__ __launch_bounds__(TFPS, 1) __cluster_dims__(CLS, 1, 1)
void fps_kernel(const float* __restrict__ pos)
{
    extern __shared__ float s_tab[];
    float* s_x = s_tab;
    float* s_y = s_tab + NPTS;
    float* s_z = s_tab + 2 * NPTS;

    __shared__ unsigned long long s_mbox[2][NSLOT];  // [parity][srcCTA*NW + srcWarp]

    const int t    = threadIdx.x;
    const int w    = t >> 5;
    const int lane = t & 31;
    unsigned rank;
    asm("mov.u32 %0, %%cluster_ctarank;" : "=r"(rank));

    // one-time: local coordinate table + mailbox init
    for (int i = t; i < NPTS; i += TFPS) {
        s_x[i] = pos[i * 3 + 0];
        s_y[i] = pos[i * 3 + 1];
        s_z[i] = pos[i * 3 + 2];
    }
    if (t < 2 * NSLOT) s_mbox[t >= NSLOT][t & (NSLOT - 1)] = 0ull;
    if (rank == 0 && t == 0) g_idx[0] = 0;
    __syncthreads();
    asm volatile("barrier.cluster.arrive.aligned;" ::: "memory");
    asm volatile("barrier.cluster.wait.aligned;"   ::: "memory");

    // precomputed addresses
    const unsigned a_slot_local = smem_u32(&s_mbox[0][rank * NW + w]); // parity 0; +512B for parity 1
    const unsigned a_poll0      = smem_u32(&s_mbox[0][lane]);
    const unsigned a_poll1      = smem_u32(&s_mbox[0][lane + 32]);
    unsigned a_remote = 0;
    if (lane < CLS) {
        asm("mapa.shared::cluster.u32 %0, %1, %2;"
            : "=r"(a_remote) : "r"(a_slot_local), "r"(lane));
    }

    // this thread's PPT points: gi = base + t + j*TFPS (ascending in j)
    const int base = (int)rank * (TFPS * PPT) + t;
    float px[PPT], py[PPT], pz[PPT], dmin[PPT];
    #pragma unroll
    for (int j = 0; j < PPT; ++j) {
        int gi = base + j * TFPS;
        px[j] = s_x[gi]; py[j] = s_y[gi]; pz[j] = s_z[gi];
        dmin[j] = CUDART_INF_F;
    }
    float cx = s_x[0], cy = s_y[0], cz = s_z[0];

    for (int it = 1; it < MCTR; ++it) {
        const unsigned poff = (it & 1) ? (unsigned)(NSLOT * 8) : 0u;

        // exact reference arithmetic: ((dx*dx + dy*dy) + dz*dz), all rn, no FMA
        // thread-local argmax with first-index tie-break (ascending gi, strict >)
        float bestv = -1.0f;
        int   bestj = 0;
        #pragma unroll
        for (int j = 0; j < PPT; ++j) {
            float dx = px[j] - cx, dy = py[j] - cy, dz = pz[j] - cz;
            float d = __fadd_rn(__fadd_rn(__fmul_rn(dx, dx), __fmul_rn(dy, dy)),
                                __fmul_rn(dz, dz));
            float dm = fminf(dmin[j], d);
            dmin[j] = dm;
            if (dm > bestv) { bestv = dm; bestj = j; }
        }
        int besti = base + bestj * TFPS;

        // warp argmax: max value (nonneg float bits monotone as u32), then min index
        unsigned vb   = __float_as_uint(bestv);
        unsigned wmax = __reduce_max_sync(0xffffffffu, vb);
        int cand = (vb == wmax) ? besti : 0x7fffffff;
        int wi   = __reduce_min_sync(0xffffffffu, cand);
        unsigned long long wkey =
            ((unsigned long long)wmax << 32)
          | ((unsigned long long)(0x3FFFu - (unsigned)wi) << 12)
          | (unsigned)it;

        // push this warp's key to its slot in EVERY CTA (8 lanes, 1 instr)
        if (lane < CLS) {
            asm volatile("st.relaxed.cluster.shared::cluster.b64 [%0], %1;"
                         :: "r"(a_remote + poff), "l"(wkey) : "memory");
        }

        // poll all 64 local slots (2 per lane); u64-max fold then hi/lo REDUX
        unsigned long long k0, k1;
        for (;;) {
            k0 = lds_vol_u64(a_poll0 + poff);
            k1 = lds_vol_u64(a_poll1 + poff);
            bool ok = ((unsigned)(k0 & 0xFFFu) == (unsigned)it)
                   && ((unsigned)(k1 & 0xFFFu) == (unsigned)it);
            if (__all_sync(0xffffffffu, ok)) break;
        }
        unsigned long long k = (k0 > k1) ? k0 : k1;   // same tag -> pure key order
        unsigned hi   = (unsigned)(k >> 32);
        unsigned gmax = __reduce_max_sync(0xffffffffu, hi);
        unsigned lo   = (hi == gmax) ? (unsigned)k : 0u;
        unsigned glo  = __reduce_max_sync(0xffffffffu, lo);
        int gidx = (int)(0x3FFFu - ((glo >> 12) & 0x3FFFu));

        if (rank == 0 && w == 0 && lane == 0) g_idx[it] = gidx;  // fire-and-forget

        cx = s_x[gidx]; cy = s_y[gidx]; cz = s_z[gidx];          // broadcast LDS
    }

    // no CTA may exit while peers could still target its smem
    asm volatile("barrier.cluster.arrive.aligned;" ::: "memory");
    asm volatile("barrier.cluster.wait.aligned;"   ::: "memory");
}

// ---------------- Stage 2: ball query ----------------
#define CHUNK 2048
__global__ __launch_bounds__(256)
void nbr_kernel(const float* __restrict__ pos)
{
    __shared__ float sx[CHUNK], sy[CHUNK], sz[CHUNK];
    __shared__ int   s_ci[8][MAXC];
    __shared__ float s_cd[8][MAXC];

    const int tid  = threadIdx.x;
    const int w    = tid >> 5;
    const int lane = tid & 31;
    const int m    = blockIdx.x * 8 + w;

    const int cidx = g_idx[m];
    const float cx = pos[cidx * 3 + 0];
    const float cy = pos[cidx * 3 + 1];
    const float cz = pos[cidx * 3 + 2];

    int cnt = 0;
    for (int base = 0; base < NPTS; base += CHUNK) {
        __syncthreads();
        for (int i = tid; i < CHUNK; i += 256) {
            sx[i] = pos[(base + i) * 3 + 0];
            sy[i] = pos[(base + i) * 3 + 1];
            sz[i] = pos[(base + i) * 3 + 2];
        }
        __syncthreads();
        for (int i = lane; i < CHUNK; i += 32) {
            float dx = sx[i] - cx, dy = sy[i] - cy, dz = sz[i] - cz;
            float d2 = __fadd_rn(__fadd_rn(__fmul_rn(dx, dx), __fmul_rn(dy, dy)),
                                 __fmul_rn(dz, dz));
            bool in = (d2 <= RAD2);
            unsigned mk = __ballot_sync(0xffffffffu, in);
            int slot = cnt + __popc(mk & ((1u << lane) - 1u));
            if (in && slot < MAXC) { s_ci[w][slot] = base + i; s_cd[w][slot] = d2; }
            cnt += __popc(mk);
        }
    }
    cnt = min(cnt, MAXC);

    if (cnt <= KNBR) {
        if (lane < cnt) g_nbr[m * KNBR + lane] = s_ci[w][lane];
        if (lane == 0)  g_cnt[m] = cnt;
    } else {
        for (int c = lane; c < cnt; c += 32) {
            float d = s_cd[w][c];
            int  ii = s_ci[w][c];
            int r = 0;
            for (int o = 0; o < cnt; ++o) {
                float d2o = s_cd[w][o];
                r += (d2o < d) || (d2o == d && s_ci[w][o] < ii);
            }
            if (r < KNBR) g_nbr[m * KNBR + r] = ii;
        }
        if (lane == 0) g_cnt[m] = KNBR;
    }
}

// ---------------- Stage 3: per-edge MLP + masked max aggregation ----------------
__global__ __launch_bounds__(256)
void mlp_kernel(const float* __restrict__ feat,
                const float* __restrict__ pos,
                const float* __restrict__ W1, const float* __restrict__ b1,
                const float* __restrict__ W2, const float* __restrict__ b2,
                const float* __restrict__ W3, const float* __restrict__ b3,
                float* __restrict__ out)
{
    __shared__ float xb[32][68];
    __shared__ float h1[32][64];
    __shared__ float h2[32][64];
    __shared__ float h3[32][128];

    const int m    = blockIdx.x;
    const int tid  = threadIdx.x;
    const int w    = tid >> 5;
    const int lane = tid & 31;
    const int cnt  = g_cnt[m];

    const int cidx = g_idx[m];
    const float cx = pos[cidx * 3 + 0];
    const float cy = pos[cidx * 3 + 1];
    const float cz = pos[cidx * 3 + 2];

    for (int k = w; k < cnt; k += 8) {
        int j = g_nbr[m * KNBR + k];
        xb[k][lane]      = feat[j * FIN + lane];
        xb[k][lane + 32] = feat[j * FIN + lane + 32];
        if (lane == 0) {
            xb[k][64] = pos[j * 3 + 0] - cx;
            xb[k][65] = pos[j * 3 + 1] - cy;
            xb[k][66] = pos[j * 3 + 2] - cz;
        }
    }
    __syncthreads();

    for (int p = tid; p < cnt * 64; p += 256) {
        int k = p >> 6, o = p & 63;
        float acc = b1[o];
        #pragma unroll
        for (int i = 0; i < 67; ++i)
            acc = fmaf(xb[k][i], W1[i * 64 + o], acc);
        h1[k][o] = fmaxf(acc, 0.0f);
    }
    __syncthreads();

    for (int p = tid; p < cnt * 64; p += 256) {
        int k = p >> 6, o = p & 63;
        float acc = b2[o];
        #pragma unroll
        for (int i = 0; i < 64; ++i)
            acc = fmaf(h1[k][i], W2[i * 64 + o], acc);
        h2[k][o] = fmaxf(acc, 0.0f);
    }
    __syncthreads();

    for (int p = tid; p < cnt * 128; p += 256) {
        int k = p >> 7, o = p & 127;
        float acc = b3[o];
        #pragma unroll
        for (int i = 0; i < 64; ++i)
            acc = fmaf(h2[k][i], W3[i * 128 + o], acc);
        h3[k][o] = fmaxf(acc, 0.0f);
    }
    __syncthreads();

    if (tid < 128) {
        float mx = -CUDART_INF_F;
        for (int k = 0; k < cnt; ++k) mx = fmaxf(mx, h3[k][tid]);
        out[m * 128 + tid] = mx;
    }
}

// ---------------- Stage 4: tail outputs ----------------
__global__ void tail_kernel(const float* __restrict__ pos, float* __restrict__ out,
                            int out_size)
{
    int m = blockIdx.x * blockDim.x + threadIdx.x;
    if (m >= MCTR) return;
    const int base = MCTR * 128;
    if (out_size >= base + 3 * MCTR) {
        int j = g_idx[m];
        out[base + 3 * m + 0] = pos[3 * j + 0];
        out[base + 3 * m + 1] = pos[3 * j + 1];
        out[base + 3 * m + 2] = pos[3 * j + 2];
    }
    if (out_size >= base + 3 * MCTR + MCTR) {
        out[base + 3 * MCTR + m] = 0.0f;
    }
}

extern "C" void kernel_launch(void* const* d_in, const int* in_sizes, int n_in,
                              void* d_out, int out_size)
{
    const float* feat = (const float*)d_in[0];
    const float* pos  = (const float*)d_in[1];
    const float* W1 = (const float*)d_in[3];
    const float* b1 = (const float*)d_in[4];
    const float* W2 = (const float*)d_in[5];
    const float* b2 = (const float*)d_in[6];
    const float* W3 = (const float*)d_in[7];
    const float* b3 = (const float*)d_in[8];
    float* out = (float*)d_out;

    const size_t fps_smem = 3 * NPTS * sizeof(float);   // 192KB
    cudaFuncSetAttribute(fps_kernel, cudaFuncAttributeMaxDynamicSharedMemorySize,
                         (int)fps_smem);

    fps_kernel<<<CLS, TFPS, fps_smem>>>(pos);
    nbr_kernel<<<MCTR / 8, 256>>>(pos);
    mlp_kernel<<<MCTR, 256>>>(feat, pos, W1, b1, W2, b2, W3, b3, out);
    tail_kernel<<<(MCTR + 255) / 256, 256>>>(pos, out, out_size);
}